// round 15
// baseline (speedup 1.0000x reference)
#include <cuda_runtime.h>

#define TPB 64
#define BPB 8
#define NBATCH 262144

typedef unsigned long long u64;

__device__ __forceinline__ u64 f2fma(u64 a, u64 b, u64 c) {
    u64 d; asm("fma.rn.f32x2 %0, %1, %2, %3;" : "=l"(d) : "l"(a), "l"(b), "l"(c)); return d;
}
__device__ __forceinline__ u64 f2add(u64 a, u64 b) {
    u64 d; asm("add.rn.f32x2 %0, %1, %2;" : "=l"(d) : "l"(a), "l"(b)); return d;
}
__device__ __forceinline__ u64 f2mul(u64 a, u64 b) {
    u64 d; asm("mul.rn.f32x2 %0, %1, %2;" : "=l"(d) : "l"(a), "l"(b)); return d;
}
__device__ __forceinline__ u64 f2bcast(float x) {
    u64 d; asm("mov.b64 %0, {%1, %1};" : "=l"(d) : "f"(x)); return d;
}
__device__ __forceinline__ u64 f2pk(float x, float y) {
    u64 d; asm("mov.b64 %0, {%1, %2};" : "=l"(d) : "f"(x), "f"(y)); return d;
}
__device__ __forceinline__ float f2lo(u64 a) {
    float x, y; asm("mov.b64 {%0, %1}, %2;" : "=f"(x), "=f"(y) : "l"(a)); return x;
}
__device__ __forceinline__ float f2hi(u64 a) {
    float x, y; asm("mov.b64 {%0, %1}, %2;" : "=f"(x), "=f"(y) : "l"(a)); return y;
}
__device__ __forceinline__ float fext(u64 a, int h) { return h ? f2hi(a) : f2lo(a); }
__device__ __forceinline__ float fex2(float x) {
    float r; asm("ex2.approx.f32 %0, %1;" : "=f"(r) : "f"(x)); return r;
}
__device__ __forceinline__ float frcp(float x) {
    float r; asm("rcp.approx.f32 %0, %1;" : "=f"(r) : "f"(x)); return r;
}

// Pre-packed weight image: [seg][e 0..9 (9 = bias)][c 0..4 K-pairs, 5..9 V-pairs]
__device__ u64 g_wpack[400];
__device__ u64 g_lng[5];   // ln_g pairs (pad 0)
__device__ u64 g_lnb[5];   // ln_b pairs (pad 0)

__global__ void pack_kernel(
    const float* __restrict__ W_jk, const float* __restrict__ b_jk,
    const float* __restrict__ W_ok, const float* __restrict__ b_ok,
    const float* __restrict__ W_gk, const float* __restrict__ b_gk,
    const float* __restrict__ W_bk, const float* __restrict__ b_bk,
    const float* __restrict__ W_jv, const float* __restrict__ b_jv,
    const float* __restrict__ W_ov, const float* __restrict__ b_ov,
    const float* __restrict__ W_gv, const float* __restrict__ b_gv,
    const float* __restrict__ W_bv, const float* __restrict__ b_bv,
    const float* __restrict__ ln_g, const float* __restrict__ ln_b)
{
    const int idx = threadIdx.x;
    if (idx < 400) {
        const float SQL2E = 1.2011224087864498f;  // sqrt(log2 e)
        const float* Wp[8] = {W_jk, W_ok, W_gk, W_bk, W_jv, W_ov, W_gv, W_bv};
        const float* Bp[8] = {b_jk, b_ok, b_gk, b_bk, b_jv, b_ov, b_gv, b_bv};
        int s = idx / 100, e = (idx % 100) / 10, c = idx % 10;
        int isK = (c < 5);
        int m = isK ? 0 : 4;
        int p = isK ? c : c - 5;
        float lo, hi;
        if (e < 9) {
            const float* W = Wp[m + s];
            lo = W[(2 * p) * 9 + e];
            hi = (2 * p + 1 < 9) ? W[(2 * p + 1) * 9 + e] : 0.f;
        } else {
            const float* B = Bp[m + s];
            lo = B[2 * p];
            hi = (2 * p + 1 < 9) ? B[2 * p + 1] : 0.f;
        }
        if (isK) { lo *= SQL2E; hi *= SQL2E; }
        g_wpack[idx] = f2pk(lo, hi);
    } else if (idx < 410) {
        int p = idx - 400;
        if (p < 5) {
            float lo = ln_g[2 * p];
            float hi = (2 * p + 1 < 9) ? ln_g[2 * p + 1] : 0.f;
            g_lng[p] = f2pk(lo, hi);
        } else {
            p -= 5;
            float lo = ln_b[2 * p];
            float hi = (2 * p + 1 < 9) ? ln_b[2 * p + 1] : 0.f;
            g_lnb[p] = f2pk(lo, hi);
        }
    }
}

// 5x LDG.128 of one packed weight row (L1-resident, broadcast across quads)
#define LOADROW(P, PTR) \
    ulonglong2 P##_01 = *(const ulonglong2*)((PTR) + 0); \
    ulonglong2 P##_23 = *(const ulonglong2*)((PTR) + 2); \
    ulonglong2 P##_45 = *(const ulonglong2*)((PTR) + 4); \
    ulonglong2 P##_67 = *(const ulonglong2*)((PTR) + 6); \
    ulonglong2 P##_89 = *(const ulonglong2*)((PTR) + 8);

#define PROJ(K, V, P, BC) \
    K[0] = f2fma(P##_01.x, BC, K[0]); K[1] = f2fma(P##_01.y, BC, K[1]); \
    K[2] = f2fma(P##_23.x, BC, K[2]); K[3] = f2fma(P##_23.y, BC, K[3]); \
    K[4] = f2fma(P##_45.x, BC, K[4]); \
    V[0] = f2fma(P##_45.y, BC, V[0]); V[1] = f2fma(P##_67.x, BC, V[1]); \
    V[2] = f2fma(P##_67.y, BC, V[2]); V[3] = f2fma(P##_89.x, BC, V[3]); \
    V[4] = f2fma(P##_89.y, BC, V[4]);

#define TILELOAD(PTR) \
    ulonglong2 c0 = *(const ulonglong2*)((PTR) + 0); \
    ulonglong2 c1 = *(const ulonglong2*)((PTR) + 2); \
    ulonglong2 c2 = *(const ulonglong2*)((PTR) + 4); \
    ulonglong2 c3 = *(const ulonglong2*)((PTR) + 6); \
    ulonglong2 c4 = *(const ulonglong2*)((PTR) + 8); \
    ulonglong2 c5 = *(const ulonglong2*)((PTR) + 10); \
    u64 c6 = (PTR)[12];

#define ACC13(SS, KQ) \
    SS[0]  = f2fma(c0.x, KQ, SS[0]);  SS[1]  = f2fma(c0.y, KQ, SS[1]); \
    SS[2]  = f2fma(c1.x, KQ, SS[2]);  SS[3]  = f2fma(c1.y, KQ, SS[3]); \
    SS[4]  = f2fma(c2.x, KQ, SS[4]);  SS[5]  = f2fma(c2.y, KQ, SS[5]); \
    SS[6]  = f2fma(c3.x, KQ, SS[6]);  SS[7]  = f2fma(c3.y, KQ, SS[7]); \
    SS[8]  = f2fma(c4.x, KQ, SS[8]);  SS[9]  = f2fma(c4.y, KQ, SS[9]); \
    SS[10] = f2fma(c5.x, KQ, SS[10]); SS[11] = f2fma(c5.y, KQ, SS[11]); \
    SS[12] = f2fma(c6,   KQ, SS[12]);

// accumulate prob-pair (PL low j, PH high j) against V rows a (j=2jp) and b (j=2jp+1)
#define AVJ(Y, PL, PH) { \
    u64 wl = f2bcast(PL); \
    Y[0] = f2fma(a01.x, wl, Y[0]); Y[1] = f2fma(a01.y, wl, Y[1]); \
    Y[2] = f2fma(a23.x, wl, Y[2]); Y[3] = f2fma(a23.y, wl, Y[3]); \
    Y[4] = f2fma(a4,    wl, Y[4]); \
    u64 wh = f2bcast(PH); \
    Y[0] = f2fma(b01.x, wh, Y[0]); Y[1] = f2fma(b01.y, wh, Y[1]); \
    Y[2] = f2fma(b23.x, wh, Y[2]); Y[3] = f2fma(b23.y, wh, Y[3]); \
    Y[4] = f2fma(b4,    wh, Y[4]); }

// dynamic smem layout (bytes), BPB=8:
//   [0, 7200)        sX  : x staging (BPB*225 floats) — alive the WHOLE kernel
//   [7200, 15264)    sKt : K tiles d-major [BPB][9][14] u64; reused as out staging
//   [15264, 26016)   sV  : V rows j-major [BPB][28][6] u64
#define OFF_X   0
#define OFF_KT  7200
#define OFF_V   15264
#define SMEM_TOTAL 26016

__global__ __launch_bounds__(TPB, 7)
void attn_submodule_kernel(const float* __restrict__ x, float* __restrict__ out)
{
    extern __shared__ __align__(16) char smem[];
    float* sXf = (float*)(smem + OFF_X);

    const int t = threadIdx.x;

    // ---- prologue: coop x staging ONLY (weights pre-packed in gmem) ----
    {
        const float4* gx = (const float4*)(x + (size_t)blockIdx.x * (BPB * 225));
        float4* sx4 = (float4*)sXf;
#pragma unroll
        for (int idx = t; idx < (BPB * 225) / 4; idx += TPB) sx4[idx] = gx[idx];
    }
    __syncthreads();

    // ---- per-thread: one batch, one SEGMENT-PURE quad of query rows ----
    // i: 0->q0=0(n3,s0) 1->3(n4,s1) 2->7(n4,s1) 3->11(n2,s1)
    //    4->13(n4,s2) 5->17(n4,s2) 6->21(n2,s2) 7->23(n2,s3)
    const int bi = t >> 3;
    const int i  = t & 7;
    const int q0  = (int)((0x1715110D0B070300ULL >> (8 * i)) & 0xFF);
    const int n   = (int)((0x0202040402040403ULL >> (8 * i)) & 0xFF);
    const int seg = (int)((0x0302020201010100ULL >> (8 * i)) & 0xFF);

    const float af2 = (n > 2) ? 1.f : 0.f;
    const float af3 = (n > 3) ? 1.f : 0.f;
    const bool st2 = (n > 2) || (q0 + 2 == 25);  // i=7 writes zero pad at col/row 25
    const bool st3 = (n > 3);

    const float* xb = sXf + bi * 225;
    const int r2 = min(q0 + 2, 24), r3 = min(q0 + 3, 24);

    // Stage A: K,V projection, single weight set; weights via LDG from packed image.
    // Accumulators initialized from the bias row (e=9), masked for dead slots.
    u64 K0[5], K1[5], K2[5], K3[5], V0[5], V1[5], V2[5], V3[5];
    {
        const u64* __restrict__ wS = g_wpack + seg * 100;
        {
            LOADROW(A, wS + 90)
            u64 m2 = f2bcast(af2), m3 = f2bcast(af3);
            K0[0] = A_01.x; K0[1] = A_01.y; K0[2] = A_23.x; K0[3] = A_23.y; K0[4] = A_45.x;
            V0[0] = A_45.y; V0[1] = A_67.x; V0[2] = A_67.y; V0[3] = A_89.x; V0[4] = A_89.y;
#pragma unroll
            for (int p = 0; p < 5; p++) {
                K1[p] = K0[p];            V1[p] = V0[p];
                K2[p] = f2mul(K0[p], m2); V2[p] = f2mul(V0[p], m2);
                K3[p] = f2mul(K0[p], m3); V3[p] = f2mul(V0[p], m3);
            }
        }
#pragma unroll
        for (int e = 0; e < 9; e++) {
            LOADROW(A, wS + e * 10)
            u64 b0 = f2bcast(xb[q0 * 9 + e]);
            u64 b1 = f2bcast(xb[(q0 + 1) * 9 + e]);
            u64 b2 = f2bcast(xb[r2 * 9 + e] * af2);
            u64 b3 = f2bcast(xb[r3 * 9 + e] * af3);
            PROJ(K0, V0, A, b0)
            PROJ(K1, V1, A, b1)
            PROJ(K2, V2, A, b2)
            PROJ(K3, V3, A, b3)
        }
    }

    // transpose stores: K d-major (scalar, guarded), V padded rows (6 u64 each)
    {
        float* ktf = (float*)(smem + OFF_KT) + bi * 252;
#pragma unroll
        for (int d = 0; d < 9; d++) {
            const int p = d >> 1, h = d & 1;
            ktf[d * 28 + q0]     = fext(K0[p], h);
            ktf[d * 28 + q0 + 1] = fext(K1[p], h);
            if (st2) ktf[d * 28 + q0 + 2] = fext(K2[p], h);
            if (st3) ktf[d * 28 + q0 + 3] = fext(K3[p], h);
        }
        u64* vb = (u64*)(smem + OFF_V) + (size_t)bi * 168;  // 28 rows * 6 u64
        u64* r0p = vb + (size_t)q0 * 6;
        *(ulonglong2*)(r0p + 0) = make_ulonglong2(V0[0], V0[1]);
        *(ulonglong2*)(r0p + 2) = make_ulonglong2(V0[2], V0[3]);
        r0p[4] = V0[4];
        u64* r1p = vb + (size_t)(q0 + 1) * 6;
        *(ulonglong2*)(r1p + 0) = make_ulonglong2(V1[0], V1[1]);
        *(ulonglong2*)(r1p + 2) = make_ulonglong2(V1[2], V1[3]);
        r1p[4] = V1[4];
        if (st2) {
            u64* r2p = vb + (size_t)(q0 + 2) * 6;
            *(ulonglong2*)(r2p + 0) = make_ulonglong2(V2[0], V2[1]);
            *(ulonglong2*)(r2p + 2) = make_ulonglong2(V2[2], V2[3]);
            r2p[4] = V2[4];
        }
        if (st3) {
            u64* r3p = vb + (size_t)(q0 + 3) * 6;
            *(ulonglong2*)(r3p + 0) = make_ulonglong2(V3[0], V3[1]);
            *(ulonglong2*)(r3p + 2) = make_ulonglong2(V3[2], V3[3]);
            r3p[4] = V3[4];
        }
    }
    __syncthreads();

    // Stage B: 4 score rows over 13 key-pairs (scores pre-scaled by log2 e)
    u64 ss0[13], ss1[13], ss2[13], ss3[13];
#pragma unroll
    for (int jp = 0; jp < 13; jp++) { ss0[jp] = 0ULL; ss1[jp] = 0ULL; ss2[jp] = 0ULL; ss3[jp] = 0ULL; }
    {
        const u64* ktb = (const u64*)(smem + OFF_KT) + (size_t)bi * 126;
#pragma unroll
        for (int d = 0; d < 9; d++) {
            const u64* kr = ktb + d * 14;
            TILELOAD(kr)
            const int p = d >> 1, h = d & 1;
            u64 kq0 = f2bcast(fext(K0[p], h));
            u64 kq1 = f2bcast(fext(K1[p], h));
            u64 kq2 = f2bcast(fext(K2[p], h));
            u64 kq3 = f2bcast(fext(K3[p], h));
            ACC13(ss0, kq0)
            ACC13(ss1, kq1)
            ACC13(ss2, kq2)
            ACC13(ss3, kq3)
        }
    }

    // Stage C+D fused, jp-outer: prob-pair -> psum + attn@V
    u64 Y0[5], Y1[5], Y2[5], Y3[5];
#pragma unroll
    for (int p = 0; p < 5; p++) { Y0[p] = Y1[p] = Y2[p] = Y3[p] = 0ULL; }
    u64 P0 = 0ULL, P1 = 0ULL, P2 = 0ULL, P3 = 0ULL;
    {
        const u64* vb = (const u64*)(smem + OFF_V) + (size_t)bi * 168;
#pragma unroll
        for (int jp = 0; jp < 13; jp++) {
            float p0l = fex2(f2lo(ss0[jp])), p0h = (jp < 12) ? fex2(f2hi(ss0[jp])) : 0.f;
            float p1l = fex2(f2lo(ss1[jp])), p1h = (jp < 12) ? fex2(f2hi(ss1[jp])) : 0.f;
            float p2l = fex2(f2lo(ss2[jp])), p2h = (jp < 12) ? fex2(f2hi(ss2[jp])) : 0.f;
            float p3l = fex2(f2lo(ss3[jp])), p3h = (jp < 12) ? fex2(f2hi(ss3[jp])) : 0.f;
            P0 = f2add(P0, f2pk(p0l, p0h));
            P1 = f2add(P1, f2pk(p1l, p1h));
            P2 = f2add(P2, f2pk(p2l, p2h));
            P3 = f2add(P3, f2pk(p3l, p3h));
            const u64* ra = vb + (size_t)(2 * jp) * 6;
            const u64* rb = vb + (size_t)(2 * jp + 1) * 6;
            ulonglong2 a01 = *(const ulonglong2*)(ra);
            ulonglong2 a23 = *(const ulonglong2*)(ra + 2);
            u64 a4 = ra[4];
            ulonglong2 b01 = *(const ulonglong2*)(rb);
            ulonglong2 b23 = *(const ulonglong2*)(rb + 2);
            u64 b4 = rb[4];
            AVJ(Y0, p0l, p0h)
            AVJ(Y1, p1l, p1h)
            AVJ(Y2, p2l, p2h)
            AVJ(Y3, p3l, p3h)
        }
    }
    const float rinv0 = frcp(f2lo(P0) + f2hi(P0));
    const float rinv1 = frcp(f2lo(P1) + f2hi(P1));
    const float rinv2 = frcp(f2lo(P2) + f2hi(P2));
    const float rinv3 = frcp(f2lo(P3) + f2hi(P3));

    // sKt dead after stage B for all threads -> reuse as output staging.
    // x residual is RE-READ from sX (still valid).
    __syncthreads();

    // gamma/beta: vector LDG from packed pairs, AFTER the barrier (shorter live range)
    u64 gv[5], bv[5];
    {
        ulonglong2 t0 = *(const ulonglong2*)(g_lng + 0);
        ulonglong2 t1 = *(const ulonglong2*)(g_lng + 2);
        gv[0] = t0.x; gv[1] = t0.y; gv[2] = t1.x; gv[3] = t1.y; gv[4] = g_lng[4];
        ulonglong2 t2 = *(const ulonglong2*)(g_lnb + 0);
        ulonglong2 t3 = *(const ulonglong2*)(g_lnb + 2);
        bv[0] = t2.x; bv[1] = t2.y; bv[2] = t3.x; bv[3] = t3.y; bv[4] = g_lnb[4];
    }

    {
        float* ko = (float*)(smem + OFF_KT) + bi * 225;

#define FINSLOT(YV, RINV, QIDX) { \
        float yv[9]; float sm = 0.f; \
        _Pragma("unroll") \
        for (int d = 0; d < 9; d++) { \
            yv[d] = fmaf(fext(YV[d >> 1], d & 1), RINV, xb[(QIDX) * 9 + d]); \
            sm += yv[d]; \
        } \
        float mu = sm * (1.f / 9.f); \
        float vq = 0.f; \
        _Pragma("unroll") \
        for (int d = 0; d < 9; d++) { float a = yv[d] - mu; vq = fmaf(a, a, vq); } \
        float rs = rsqrtf(vq * (1.f / 9.f) + 1e-5f); \
        float* o = ko + (QIDX) * 9; \
        _Pragma("unroll") \
        for (int d = 0; d < 9; d++) \
            o[d] = fmaf((yv[d] - mu) * rs, fext(gv[d >> 1], d & 1), fext(bv[d >> 1], d & 1)); }

        FINSLOT(Y0, rinv0, q0)
        FINSLOT(Y1, rinv1, q0 + 1)
        if (n > 2) { FINSLOT(Y2, rinv2, q0 + 2) }
        if (n > 3) { FINSLOT(Y3, rinv3, q0 + 3) }
#undef FINSLOT
    }
    __syncthreads();

    // Coalesced float4 store of the whole block's output
    {
        float4* gout = (float4*)(out + (size_t)blockIdx.x * (BPB * 225));
        const float4* so4 = (const float4*)(smem + OFF_KT);
#pragma unroll
        for (int idx = t; idx < (BPB * 225) / 4; idx += TPB) gout[idx] = so4[idx];
    }
}

extern "C" void kernel_launch(void* const* d_in, const int* in_sizes, int n_in,
                              void* d_out, int out_size)
{
    (void)in_sizes; (void)n_in; (void)out_size;
    const float* x    = (const float*)d_in[0];
    const float* W_jk = (const float*)d_in[1];
    const float* b_jk = (const float*)d_in[2];
    const float* W_ok = (const float*)d_in[3];
    const float* b_ok = (const float*)d_in[4];
    const float* W_gk = (const float*)d_in[5];
    const float* b_gk = (const float*)d_in[6];
    const float* W_bk = (const float*)d_in[7];
    const float* b_bk = (const float*)d_in[8];
    const float* W_jv = (const float*)d_in[9];
    const float* b_jv = (const float*)d_in[10];
    const float* W_ov = (const float*)d_in[11];
    const float* b_ov = (const float*)d_in[12];
    const float* W_gv = (const float*)d_in[13];
    const float* b_gv = (const float*)d_in[14];
    const float* W_bv = (const float*)d_in[15];
    const float* b_bv = (const float*)d_in[16];
    const float* ln_g = (const float*)d_in[17];
    const float* ln_b = (const float*)d_in[18];
    float* out = (float*)d_out;

    pack_kernel<<<1, 512>>>(W_jk, b_jk, W_ok, b_ok, W_gk, b_gk, W_bk, b_bk,
                            W_jv, b_jv, W_ov, b_ov, W_gv, b_gv, W_bv, b_bv,
                            ln_g, ln_b);

    cudaFuncSetAttribute(attn_submodule_kernel,
                         cudaFuncAttributeMaxDynamicSharedMemorySize, SMEM_TOTAL);
    dim3 grid(NBATCH / BPB);
    dim3 block(TPB);
    attn_submodule_kernel<<<grid, block, SMEM_TOTAL>>>(x, out);
}

// round 16
// speedup vs baseline: 1.4106x; 1.4106x over previous
#include <cuda_runtime.h>

#define TPB 128
#define BPB 16
#define NBATCH 262144

typedef unsigned long long u64;

__device__ __forceinline__ u64 f2fma(u64 a, u64 b, u64 c) {
    u64 d; asm("fma.rn.f32x2 %0, %1, %2, %3;" : "=l"(d) : "l"(a), "l"(b), "l"(c)); return d;
}
__device__ __forceinline__ u64 f2add(u64 a, u64 b) {
    u64 d; asm("add.rn.f32x2 %0, %1, %2;" : "=l"(d) : "l"(a), "l"(b)); return d;
}
__device__ __forceinline__ u64 f2mul(u64 a, u64 b) {
    u64 d; asm("mul.rn.f32x2 %0, %1, %2;" : "=l"(d) : "l"(a), "l"(b)); return d;
}
__device__ __forceinline__ u64 f2bcast(float x) {
    u64 d; asm("mov.b64 %0, {%1, %1};" : "=l"(d) : "f"(x)); return d;
}
__device__ __forceinline__ u64 f2pk(float x, float y) {
    u64 d; asm("mov.b64 %0, {%1, %2};" : "=l"(d) : "f"(x), "f"(y)); return d;
}
__device__ __forceinline__ float f2lo(u64 a) {
    float x, y; asm("mov.b64 {%0, %1}, %2;" : "=f"(x), "=f"(y) : "l"(a)); return x;
}
__device__ __forceinline__ float f2hi(u64 a) {
    float x, y; asm("mov.b64 {%0, %1}, %2;" : "=f"(x), "=f"(y) : "l"(a)); return y;
}
__device__ __forceinline__ float fext(u64 a, int h) { return h ? f2hi(a) : f2lo(a); }
__device__ __forceinline__ float fex2(float x) {
    float r; asm("ex2.approx.f32 %0, %1;" : "=f"(r) : "f"(x)); return r;
}
__device__ __forceinline__ float frcp(float x) {
    float r; asm("rcp.approx.f32 %0, %1;" : "=f"(r) : "f"(x)); return r;
}

// Pre-packed weight image: [seg][e 0..9 (9 = bias)][c 0..4 K-pairs, 5..9 V-pairs]
__device__ u64 g_wpack[400];
__device__ u64 g_lng[5];   // ln_g pairs (pad 0)
__device__ u64 g_lnb[5];   // ln_b pairs (pad 0)

__global__ void pack_kernel(
    const float* __restrict__ W_jk, const float* __restrict__ b_jk,
    const float* __restrict__ W_ok, const float* __restrict__ b_ok,
    const float* __restrict__ W_gk, const float* __restrict__ b_gk,
    const float* __restrict__ W_bk, const float* __restrict__ b_bk,
    const float* __restrict__ W_jv, const float* __restrict__ b_jv,
    const float* __restrict__ W_ov, const float* __restrict__ b_ov,
    const float* __restrict__ W_gv, const float* __restrict__ b_gv,
    const float* __restrict__ W_bv, const float* __restrict__ b_bv,
    const float* __restrict__ ln_g, const float* __restrict__ ln_b)
{
    const int idx = threadIdx.x;
    if (idx < 400) {
        const float SQL2E = 1.2011224087864498f;  // sqrt(log2 e)
        const float* Wp[8] = {W_jk, W_ok, W_gk, W_bk, W_jv, W_ov, W_gv, W_bv};
        const float* Bp[8] = {b_jk, b_ok, b_gk, b_bk, b_jv, b_ov, b_gv, b_bv};
        int s = idx / 100, e = (idx % 100) / 10, c = idx % 10;
        int isK = (c < 5);
        int m = isK ? 0 : 4;
        int p = isK ? c : c - 5;
        float lo, hi;
        if (e < 9) {
            const float* W = Wp[m + s];
            lo = W[(2 * p) * 9 + e];
            hi = (2 * p + 1 < 9) ? W[(2 * p + 1) * 9 + e] : 0.f;
        } else {
            const float* B = Bp[m + s];
            lo = B[2 * p];
            hi = (2 * p + 1 < 9) ? B[2 * p + 1] : 0.f;
        }
        if (isK) { lo *= SQL2E; hi *= SQL2E; }
        g_wpack[idx] = f2pk(lo, hi);
    } else if (idx < 410) {
        int p = idx - 400;
        if (p < 5) {
            float lo = ln_g[2 * p];
            float hi = (2 * p + 1 < 9) ? ln_g[2 * p + 1] : 0.f;
            g_lng[p] = f2pk(lo, hi);
        } else {
            p -= 5;
            float lo = ln_b[2 * p];
            float hi = (2 * p + 1 < 9) ? ln_b[2 * p + 1] : 0.f;
            g_lnb[p] = f2pk(lo, hi);
        }
    }
}

// 5x LDG.128 of one packed weight row (L1-resident, broadcast across quads)
#define LOADROW(P, PTR) \
    ulonglong2 P##_01 = *(const ulonglong2*)((PTR) + 0); \
    ulonglong2 P##_23 = *(const ulonglong2*)((PTR) + 2); \
    ulonglong2 P##_45 = *(const ulonglong2*)((PTR) + 4); \
    ulonglong2 P##_67 = *(const ulonglong2*)((PTR) + 6); \
    ulonglong2 P##_89 = *(const ulonglong2*)((PTR) + 8);

#define PROJ(K, V, P, BC) \
    K[0] = f2fma(P##_01.x, BC, K[0]); K[1] = f2fma(P##_01.y, BC, K[1]); \
    K[2] = f2fma(P##_23.x, BC, K[2]); K[3] = f2fma(P##_23.y, BC, K[3]); \
    K[4] = f2fma(P##_45.x, BC, K[4]); \
    V[0] = f2fma(P##_45.y, BC, V[0]); V[1] = f2fma(P##_67.x, BC, V[1]); \
    V[2] = f2fma(P##_67.y, BC, V[2]); V[3] = f2fma(P##_89.x, BC, V[3]); \
    V[4] = f2fma(P##_89.y, BC, V[4]);

#define TILELOAD(PTR) \
    ulonglong2 c0 = *(const ulonglong2*)((PTR) + 0); \
    ulonglong2 c1 = *(const ulonglong2*)((PTR) + 2); \
    ulonglong2 c2 = *(const ulonglong2*)((PTR) + 4); \
    ulonglong2 c3 = *(const ulonglong2*)((PTR) + 6); \
    ulonglong2 c4 = *(const ulonglong2*)((PTR) + 8); \
    ulonglong2 c5 = *(const ulonglong2*)((PTR) + 10); \
    u64 c6 = (PTR)[12];

#define ACC13(SS, KQ) \
    SS[0]  = f2fma(c0.x, KQ, SS[0]);  SS[1]  = f2fma(c0.y, KQ, SS[1]); \
    SS[2]  = f2fma(c1.x, KQ, SS[2]);  SS[3]  = f2fma(c1.y, KQ, SS[3]); \
    SS[4]  = f2fma(c2.x, KQ, SS[4]);  SS[5]  = f2fma(c2.y, KQ, SS[5]); \
    SS[6]  = f2fma(c3.x, KQ, SS[6]);  SS[7]  = f2fma(c3.y, KQ, SS[7]); \
    SS[8]  = f2fma(c4.x, KQ, SS[8]);  SS[9]  = f2fma(c4.y, KQ, SS[9]); \
    SS[10] = f2fma(c5.x, KQ, SS[10]); SS[11] = f2fma(c5.y, KQ, SS[11]); \
    SS[12] = f2fma(c6,   KQ, SS[12]);

// accumulate prob-pair (PL low j, PH high j) against V rows a (j=2jp) and b (j=2jp+1)
#define AVJ(Y, PL, PH) { \
    u64 wl = f2bcast(PL); \
    Y[0] = f2fma(a01.x, wl, Y[0]); Y[1] = f2fma(a01.y, wl, Y[1]); \
    Y[2] = f2fma(a23.x, wl, Y[2]); Y[3] = f2fma(a23.y, wl, Y[3]); \
    Y[4] = f2fma(a4,    wl, Y[4]); \
    u64 wh = f2bcast(PH); \
    Y[0] = f2fma(b01.x, wh, Y[0]); Y[1] = f2fma(b01.y, wh, Y[1]); \
    Y[2] = f2fma(b23.x, wh, Y[2]); Y[3] = f2fma(b23.y, wh, Y[3]); \
    Y[4] = f2fma(b4,    wh, Y[4]); }

// dynamic smem layout (bytes):
//   [0, 14400)       sX  : x staging (BPB*225 floats) — alive the WHOLE kernel
//   [14400, 30528)   sKt : K tiles d-major [BPB][9][14] u64; reused as out staging
//   [30528, 52032)   sV  : V rows j-major [BPB][28][6] u64
// NOTE: warp w owns batches bi in [4w, 4w+4) — all sKt/sV traffic is warp-local,
// so the interior barriers are __syncwarp; only x staging and the final copy
// are block-wide.
#define OFF_X   0
#define OFF_KT  14400
#define OFF_V   30528
#define SMEM_TOTAL 52032

__global__ __launch_bounds__(TPB, 3)
void attn_submodule_kernel(const float* __restrict__ x, float* __restrict__ out)
{
    extern __shared__ __align__(16) char smem[];
    float* sXf = (float*)(smem + OFF_X);

    const int t = threadIdx.x;

    // ---- prologue: coop x staging ONLY (weights pre-packed in gmem) ----
    {
        const float4* gx = (const float4*)(x + (size_t)blockIdx.x * (BPB * 225));
        float4* sx4 = (float4*)sXf;
#pragma unroll
        for (int idx = t; idx < (BPB * 225) / 4; idx += TPB) sx4[idx] = gx[idx];
    }
    __syncthreads();

    // ---- per-thread: one batch, one SEGMENT-PURE quad of query rows ----
    // i: 0->q0=0(n3,s0) 1->3(n4,s1) 2->7(n4,s1) 3->11(n2,s1)
    //    4->13(n4,s2) 5->17(n4,s2) 6->21(n2,s2) 7->23(n2,s3)
    const int bi = t >> 3;
    const int i  = t & 7;
    const int q0  = (int)((0x1715110D0B070300ULL >> (8 * i)) & 0xFF);
    const int n   = (int)((0x0202040402040403ULL >> (8 * i)) & 0xFF);
    const int seg = (int)((0x0302020201010100ULL >> (8 * i)) & 0xFF);

    const float af2 = (n > 2) ? 1.f : 0.f;
    const float af3 = (n > 3) ? 1.f : 0.f;
    const bool st2 = (n > 2) || (q0 + 2 == 25);  // i=7 writes zero pad at col/row 25
    const bool st3 = (n > 3);

    const float* xb = sXf + bi * 225;
    const int r2 = min(q0 + 2, 24), r3 = min(q0 + 3, 24);

    // Stage A: K,V projection, single weight set; weights via LDG from packed image.
    // Accumulators initialized from the bias row (e=9), masked for dead slots.
    u64 K0[5], K1[5], K2[5], K3[5], V0[5], V1[5], V2[5], V3[5];
    {
        const u64* __restrict__ wS = g_wpack + seg * 100;
        {
            LOADROW(A, wS + 90)
            u64 m2 = f2bcast(af2), m3 = f2bcast(af3);
            K0[0] = A_01.x; K0[1] = A_01.y; K0[2] = A_23.x; K0[3] = A_23.y; K0[4] = A_45.x;
            V0[0] = A_45.y; V0[1] = A_67.x; V0[2] = A_67.y; V0[3] = A_89.x; V0[4] = A_89.y;
#pragma unroll
            for (int p = 0; p < 5; p++) {
                K1[p] = K0[p];            V1[p] = V0[p];
                K2[p] = f2mul(K0[p], m2); V2[p] = f2mul(V0[p], m2);
                K3[p] = f2mul(K0[p], m3); V3[p] = f2mul(V0[p], m3);
            }
        }
#pragma unroll
        for (int e = 0; e < 9; e++) {
            LOADROW(A, wS + e * 10)
            u64 b0 = f2bcast(xb[q0 * 9 + e]);
            u64 b1 = f2bcast(xb[(q0 + 1) * 9 + e]);
            u64 b2 = f2bcast(xb[r2 * 9 + e] * af2);
            u64 b3 = f2bcast(xb[r3 * 9 + e] * af3);
            PROJ(K0, V0, A, b0)
            PROJ(K1, V1, A, b1)
            PROJ(K2, V2, A, b2)
            PROJ(K3, V3, A, b3)
        }
    }

    // transpose stores: K d-major (scalar, guarded), V padded rows (6 u64 each)
    {
        float* ktf = (float*)(smem + OFF_KT) + bi * 252;
#pragma unroll
        for (int d = 0; d < 9; d++) {
            const int p = d >> 1, h = d & 1;
            ktf[d * 28 + q0]     = fext(K0[p], h);
            ktf[d * 28 + q0 + 1] = fext(K1[p], h);
            if (st2) ktf[d * 28 + q0 + 2] = fext(K2[p], h);
            if (st3) ktf[d * 28 + q0 + 3] = fext(K3[p], h);
        }
        u64* vb = (u64*)(smem + OFF_V) + (size_t)bi * 168;  // 28 rows * 6 u64
        u64* r0p = vb + (size_t)q0 * 6;
        *(ulonglong2*)(r0p + 0) = make_ulonglong2(V0[0], V0[1]);
        *(ulonglong2*)(r0p + 2) = make_ulonglong2(V0[2], V0[3]);
        r0p[4] = V0[4];
        u64* r1p = vb + (size_t)(q0 + 1) * 6;
        *(ulonglong2*)(r1p + 0) = make_ulonglong2(V1[0], V1[1]);
        *(ulonglong2*)(r1p + 2) = make_ulonglong2(V1[2], V1[3]);
        r1p[4] = V1[4];
        if (st2) {
            u64* r2p = vb + (size_t)(q0 + 2) * 6;
            *(ulonglong2*)(r2p + 0) = make_ulonglong2(V2[0], V2[1]);
            *(ulonglong2*)(r2p + 2) = make_ulonglong2(V2[2], V2[3]);
            r2p[4] = V2[4];
        }
        if (st3) {
            u64* r3p = vb + (size_t)(q0 + 3) * 6;
            *(ulonglong2*)(r3p + 0) = make_ulonglong2(V3[0], V3[1]);
            *(ulonglong2*)(r3p + 2) = make_ulonglong2(V3[2], V3[3]);
            r3p[4] = V3[4];
        }
    }
    __syncwarp();   // warp-local: this warp wrote and will read only bi in [4w,4w+4)

    // Stage B: 4 score rows over 13 key-pairs (scores pre-scaled by log2 e)
    u64 ss0[13], ss1[13], ss2[13], ss3[13];
#pragma unroll
    for (int jp = 0; jp < 13; jp++) { ss0[jp] = 0ULL; ss1[jp] = 0ULL; ss2[jp] = 0ULL; ss3[jp] = 0ULL; }
    {
        const u64* ktb = (const u64*)(smem + OFF_KT) + (size_t)bi * 126;
#pragma unroll
        for (int d = 0; d < 9; d++) {
            const u64* kr = ktb + d * 14;
            TILELOAD(kr)
            const int p = d >> 1, h = d & 1;
            u64 kq0 = f2bcast(fext(K0[p], h));
            u64 kq1 = f2bcast(fext(K1[p], h));
            u64 kq2 = f2bcast(fext(K2[p], h));
            u64 kq3 = f2bcast(fext(K3[p], h));
            ACC13(ss0, kq0)
            ACC13(ss1, kq1)
            ACC13(ss2, kq2)
            ACC13(ss3, kq3)
        }
    }

    // Stage C+D fused, jp-outer: prob-pair -> psum + attn@V
    u64 Y0[5], Y1[5], Y2[5], Y3[5];
#pragma unroll
    for (int p = 0; p < 5; p++) { Y0[p] = Y1[p] = Y2[p] = Y3[p] = 0ULL; }
    u64 P0 = 0ULL, P1 = 0ULL, P2 = 0ULL, P3 = 0ULL;
    {
        const u64* vb = (const u64*)(smem + OFF_V) + (size_t)bi * 168;
#pragma unroll
        for (int jp = 0; jp < 13; jp++) {
            float p0l = fex2(f2lo(ss0[jp])), p0h = (jp < 12) ? fex2(f2hi(ss0[jp])) : 0.f;
            float p1l = fex2(f2lo(ss1[jp])), p1h = (jp < 12) ? fex2(f2hi(ss1[jp])) : 0.f;
            float p2l = fex2(f2lo(ss2[jp])), p2h = (jp < 12) ? fex2(f2hi(ss2[jp])) : 0.f;
            float p3l = fex2(f2lo(ss3[jp])), p3h = (jp < 12) ? fex2(f2hi(ss3[jp])) : 0.f;
            P0 = f2add(P0, f2pk(p0l, p0h));
            P1 = f2add(P1, f2pk(p1l, p1h));
            P2 = f2add(P2, f2pk(p2l, p2h));
            P3 = f2add(P3, f2pk(p3l, p3h));
            const u64* ra = vb + (size_t)(2 * jp) * 6;
            const u64* rb = vb + (size_t)(2 * jp + 1) * 6;
            ulonglong2 a01 = *(const ulonglong2*)(ra);
            ulonglong2 a23 = *(const ulonglong2*)(ra + 2);
            u64 a4 = ra[4];
            ulonglong2 b01 = *(const ulonglong2*)(rb);
            ulonglong2 b23 = *(const ulonglong2*)(rb + 2);
            u64 b4 = rb[4];
            AVJ(Y0, p0l, p0h)
            AVJ(Y1, p1l, p1h)
            AVJ(Y2, p2l, p2h)
            AVJ(Y3, p3l, p3h)
        }
    }
    const float rinv0 = frcp(f2lo(P0) + f2hi(P0));
    const float rinv1 = frcp(f2lo(P1) + f2hi(P1));
    const float rinv2 = frcp(f2lo(P2) + f2hi(P2));
    const float rinv3 = frcp(f2lo(P3) + f2hi(P3));

    // gamma/beta: vector LDG from packed pairs (L1-resident, broadcast)
    u64 gv[5], bv[5];
    {
        ulonglong2 t0 = *(const ulonglong2*)(g_lng + 0);
        ulonglong2 t1 = *(const ulonglong2*)(g_lng + 2);
        gv[0] = t0.x; gv[1] = t0.y; gv[2] = t1.x; gv[3] = t1.y; gv[4] = g_lng[4];
        ulonglong2 t2 = *(const ulonglong2*)(g_lnb + 0);
        ulonglong2 t3 = *(const ulonglong2*)(g_lnb + 2);
        bv[0] = t2.x; bv[1] = t2.y; bv[2] = t3.x; bv[3] = t3.y; bv[4] = g_lnb[4];
    }

    // sKt region for this warp's batches is dead after stage B (read only by this
    // warp) -> warp-local barrier suffices before reusing it as output staging.
    __syncwarp();
    {
        float* ko = (float*)(smem + OFF_KT) + bi * 225;

#define FINSLOT(YV, RINV, QIDX) { \
        float yv[9]; float sm = 0.f; \
        _Pragma("unroll") \
        for (int d = 0; d < 9; d++) { \
            yv[d] = fmaf(fext(YV[d >> 1], d & 1), RINV, xb[(QIDX) * 9 + d]); \
            sm += yv[d]; \
        } \
        float mu = sm * (1.f / 9.f); \
        float vq = 0.f; \
        _Pragma("unroll") \
        for (int d = 0; d < 9; d++) { float a = yv[d] - mu; vq = fmaf(a, a, vq); } \
        float rs = rsqrtf(vq * (1.f / 9.f) + 1e-5f); \
        float* o = ko + (QIDX) * 9; \
        _Pragma("unroll") \
        for (int d = 0; d < 9; d++) \
            o[d] = fmaf((yv[d] - mu) * rs, fext(gv[d >> 1], d & 1), fext(bv[d >> 1], d & 1)); }

        FINSLOT(Y0, rinv0, q0)
        FINSLOT(Y1, rinv1, q0 + 1)
        if (n > 2) { FINSLOT(Y2, rinv2, q0 + 2) }
        if (n > 3) { FINSLOT(Y3, rinv3, q0 + 3) }
#undef FINSLOT
    }
    __syncthreads();  // block-wide: final copy reads all batches' staging

    // Coalesced float4 store of the whole block's output
    {
        float4* gout = (float4*)(out + (size_t)blockIdx.x * (BPB * 225));
        const float4* so4 = (const float4*)(smem + OFF_KT);
#pragma unroll
        for (int idx = t; idx < (BPB * 225) / 4; idx += TPB) gout[idx] = so4[idx];
    }
}

extern "C" void kernel_launch(void* const* d_in, const int* in_sizes, int n_in,
                              void* d_out, int out_size)
{
    (void)in_sizes; (void)n_in; (void)out_size;
    const float* x    = (const float*)d_in[0];
    const float* W_jk = (const float*)d_in[1];
    const float* b_jk = (const float*)d_in[2];
    const float* W_ok = (const float*)d_in[3];
    const float* b_ok = (const float*)d_in[4];
    const float* W_gk = (const float*)d_in[5];
    const float* b_gk = (const float*)d_in[6];
    const float* W_bk = (const float*)d_in[7];
    const float* b_bk = (const float*)d_in[8];
    const float* W_jv = (const float*)d_in[9];
    const float* b_jv = (const float*)d_in[10];
    const float* W_ov = (const float*)d_in[11];
    const float* b_ov = (const float*)d_in[12];
    const float* W_gv = (const float*)d_in[13];
    const float* b_gv = (const float*)d_in[14];
    const float* W_bv = (const float*)d_in[15];
    const float* b_bv = (const float*)d_in[16];
    const float* ln_g = (const float*)d_in[17];
    const float* ln_b = (const float*)d_in[18];
    float* out = (float*)d_out;

    pack_kernel<<<1, 512>>>(W_jk, b_jk, W_ok, b_ok, W_gk, b_gk, W_bk, b_bk,
                            W_jv, b_jv, W_ov, b_ov, W_gv, b_gv, W_bv, b_bv,
                            ln_g, ln_b);

    cudaFuncSetAttribute(attn_submodule_kernel,
                         cudaFuncAttributeMaxDynamicSharedMemorySize, SMEM_TOTAL);
    dim3 grid(NBATCH / BPB);
    dim3 block(TPB);
    attn_submodule_kernel<<<grid, block, SMEM_TOTAL>>>(x, out);
}